// round 7
// baseline (speedup 1.0000x reference)
#include <cuda_runtime.h>
#include <cuda_bf16.h>
#include <cstdint>

// Problem constants
#define BATCH 1024
#define NN    156
#define NNP   160            // padded rows
#define CIN   301
#define CH    128
#define EDGES 1564
#define ETOT  (EDGES + NN)   // 1720
#define TS    132            // row stride (floats) for T and H tiles
#define ASTR  20             // layer-0 A staging row stride (floats)
#define BN_INV_SQRT 0.9999950000374997f

typedef unsigned long long ull;

// ---------------- graph scratch ---------------------------------------------
__device__ int  g_ptr[NN + 1];
__device__ int2 g_edge[ETOT];

// ---------------- packed fp32 helpers ---------------------------------------
__device__ __forceinline__ ull pack2(float lo, float hi) {
    ull r;
    asm("mov.b64 %0, {%1, %2};" : "=l"(r) : "f"(lo), "f"(hi));
    return r;
}
__device__ __forceinline__ void ffma2(ull& d, ull a, ull b) {
    asm("fma.rn.f32x2 %0, %1, %2, %0;" : "+l"(d) : "l"(a), "l"(b));
}
__device__ __forceinline__ float f4c(float4 v, int k) {
    return k == 0 ? v.x : k == 1 ? v.y : k == 2 ? v.z : v.w;
}

// ---------------- kernel 1: graph preprocessing -> packed CSC ---------------
__global__ void build_kernel(const void* __restrict__ eiv) {
    const int* e32 = (const int*)eiv;
    __shared__ int   is64;
    __shared__ float deg[NN];
    __shared__ float dinv[NN];
    __shared__ int   cnt[NN];
    __shared__ int   base[NN + 1];
    int tid = threadIdx.x;

    if (tid == 0) {
        int all_zero = 1;
        for (int i = 1; i < 129; i += 2)
            if (e32[i] != 0) { all_zero = 0; break; }
        is64 = all_zero;
    }
    if (tid < NN) { deg[tid] = 1.0f; cnt[tid] = 1; }  // self-loop
    __syncthreads();

    const int stride64 = is64;
    auto fetch = [&](int i) -> int {
        int v = e32[i << stride64];
        return min(max(v, 0), NN - 1);
    };

    for (int e = tid; e < EDGES; e += blockDim.x) {
        int cl = fetch(EDGES + e);
        atomicAdd(&deg[cl], 1.0f);
        atomicAdd(&cnt[cl], 1);
    }
    __syncthreads();
    if (tid < NN) dinv[tid] = rsqrtf(deg[tid]);
    if (tid == 0) {
        int run = 0;
        for (int n = 0; n < NN; n++) { base[n] = run; run += cnt[n]; }
        base[NN] = run;
    }
    __syncthreads();
    if (tid <= NN) g_ptr[tid] = base[tid];
    if (tid < NN) cnt[tid] = base[tid];
    __syncthreads();

    for (int e = tid; e < EDGES; e += blockDim.x) {
        int r  = fetch(e);
        int cl = fetch(EDGES + e);
        int pos = atomicAdd(&cnt[cl], 1);
        g_edge[pos] = make_int2(r, __float_as_int(dinv[r] * dinv[cl]));
    }
    __syncthreads();
    for (int n = tid; n < NN; n += blockDim.x) {
        int pos = atomicAdd(&cnt[n], 1);
        g_edge[pos] = make_int2(n, __float_as_int(dinv[n] * dinv[n]));
    }
}

// ---------------- fused GEMM phase: T = A @ W --------------------------------
// A row-major: AG ? staged [160][ASTR] double buffer : smH [160][TS].
// 512 threads; microtile 5 rows x 8 cols.
// Warp footprint 16 m-lanes x 2 n-lanes -> minimal B smem traffic.
template<bool AG>
__device__ __forceinline__ void gemm_phase(
    int tid, int K, int ktiles,
    const float* __restrict__ Aglob, const float* __restrict__ Wg,
    float* __restrict__ smT, const float* __restrict__ smH,
    float* __restrict__ smA, float* __restrict__ smW)
{
    const int warp = tid >> 5, lane = tid & 31;
    const int mt = (warp & 1) * 16 + (lane >> 1);   // 0..31
    const int nt = (warp >> 1) * 2 + (lane & 1);    // 0..15
    const int wkk = tid >> 5, wc4 = tid & 31;

    ull acc[5][4];
#pragma unroll
    for (int i = 0; i < 5; i++)
#pragma unroll
        for (int j = 0; j < 4; j++) acc[i][j] = 0ULL;

    float  areg[5];
    float4 wreg;

    // fetch + stage tile 0
    if (AG) {
#pragma unroll
        for (int p = 0; p < 5; p++) {
            int idx = tid + p * 512;
            int m = idx >> 4, kk = idx & 15;
            areg[p] = (m < NN && kk < K) ? Aglob[(size_t)m * K + kk] : 0.0f;
        }
    }
    wreg = (wkk < K) ? *(const float4*)(Wg + (size_t)wkk * CH + wc4 * 4)
                     : make_float4(0, 0, 0, 0);
    if (AG) {
#pragma unroll
        for (int p = 0; p < 5; p++) {
            int idx = tid + p * 512;
            smA[(idx >> 4) * ASTR + (idx & 15)] = areg[p];
        }
    }
    *(float4*)(smW + wkk * CH + wc4 * 4) = wreg;
    __syncthreads();

    for (int t = 0; t < ktiles; t++) {
        const int cur = t & 1, nxt = cur ^ 1;
        // prefetch next tile to registers
        if (t + 1 < ktiles) {
            const int k0 = (t + 1) * 16;
            if (AG) {
#pragma unroll
                for (int p = 0; p < 5; p++) {
                    int idx = tid + p * 512;
                    int m = idx >> 4, kk = idx & 15;
                    areg[p] = (m < NN && k0 + kk < K)
                            ? Aglob[(size_t)m * K + k0 + kk] : 0.0f;
                }
            }
            wreg = (k0 + wkk < K)
                 ? *(const float4*)(Wg + (size_t)(k0 + wkk) * CH + wc4 * 4)
                 : make_float4(0, 0, 0, 0);
        }

        const float* Ab  = AG ? (smA + cur * NNP * ASTR) : (smH + t * 16);
        const int    astr = AG ? ASTR : TS;
        const float* Bb  = smW + cur * 16 * CH;

#pragma unroll
        for (int g = 0; g < 4; g++) {
            float4 af[5];
#pragma unroll
            for (int i = 0; i < 5; i++)
                af[i] = *(const float4*)(Ab + (mt + 32 * i) * astr + g * 4);
#pragma unroll
            for (int kk = 0; kk < 4; kk++) {
                const ulonglong2* bp =
                    (const ulonglong2*)(Bb + (g * 4 + kk) * CH + nt * 8);
                ulonglong2 blo = bp[0];
                ulonglong2 bhi = bp[1];
#pragma unroll
                for (int i = 0; i < 5; i++) {
                    float a = f4c(af[i], kk);
                    ull av = pack2(a, a);
                    ffma2(acc[i][0], av, blo.x);
                    ffma2(acc[i][1], av, blo.y);
                    ffma2(acc[i][2], av, bhi.x);
                    ffma2(acc[i][3], av, bhi.y);
                }
            }
        }

        // store prefetched tile
        if (t + 1 < ktiles) {
            if (AG) {
#pragma unroll
                for (int p = 0; p < 5; p++) {
                    int idx = tid + p * 512;
                    smA[nxt * NNP * ASTR + (idx >> 4) * ASTR + (idx & 15)] = areg[p];
                }
            }
            *(float4*)(smW + nxt * 16 * CH + wkk * CH + wc4 * 4) = wreg;
        }
        __syncthreads();
    }

    // epilogue -> T row-major
#pragma unroll
    for (int i = 0; i < 5; i++) {
        float* tp = smT + (mt + 32 * i) * TS + nt * 8;
#pragma unroll
        for (int j = 0; j < 4; j++) {
            float2 v;
            v.x = __uint_as_float((unsigned)(acc[i][j] & 0xffffffffULL));
            v.y = __uint_as_float((unsigned)(acc[i][j] >> 32));
            *(float2*)(tp + 2 * j) = v;
        }
    }
}

// ---------------- fused aggregation phase ------------------------------------
// Warp-per-dst-row, lane = 4 channels (float4 gather from smT, stride 33 f4).
// BNRELU: +bias, BN, ReLU, write ROW-MAJOR into smH (conflict-free float4).
// else:   +bias, write to global out.
template<bool BNRELU>
__device__ __forceinline__ void agg_phase(
    int tid, const float* __restrict__ smT,
    float* __restrict__ smH, float* __restrict__ gout,
    const int* __restrict__ ptr, const int2* __restrict__ edg,
    const float* __restrict__ bias,
    const float* __restrict__ bnw, const float* __restrict__ bnb)
{
    const int warp = tid >> 5, lane = tid & 31;
    float4 bias4 = ((const float4*)bias)[lane];
    float4 bnw4 = make_float4(0, 0, 0, 0), bnb4 = make_float4(0, 0, 0, 0);
    if (BNRELU) {
        bnw4 = ((const float4*)bnw)[lane];
        bnw4.x *= BN_INV_SQRT; bnw4.y *= BN_INV_SQRT;
        bnw4.z *= BN_INV_SQRT; bnw4.w *= BN_INV_SQRT;
        bnb4 = ((const float4*)bnb)[lane];
    }
    const float4* T4 = (const float4*)smT;   // row stride 33 float4
    for (int n = warp; n < NN; n += 16) {
        int e = ptr[n];
        const int end = ptr[n + 1];
        float4 a0 = make_float4(0, 0, 0, 0);
        float4 a1 = make_float4(0, 0, 0, 0);
        for (; e + 1 < end; e += 2) {
            int2 e0 = edg[e], e1 = edg[e + 1];
            float4 t0 = T4[e0.x * 33 + lane];
            float4 t1 = T4[e1.x * 33 + lane];
            float m0 = __int_as_float(e0.y);
            float m1 = __int_as_float(e1.y);
            a0.x = fmaf(t0.x, m0, a0.x); a0.y = fmaf(t0.y, m0, a0.y);
            a0.z = fmaf(t0.z, m0, a0.z); a0.w = fmaf(t0.w, m0, a0.w);
            a1.x = fmaf(t1.x, m1, a1.x); a1.y = fmaf(t1.y, m1, a1.y);
            a1.z = fmaf(t1.z, m1, a1.z); a1.w = fmaf(t1.w, m1, a1.w);
        }
        if (e < end) {
            int2 e0 = edg[e];
            float4 t0 = T4[e0.x * 33 + lane];
            float m0 = __int_as_float(e0.y);
            a0.x = fmaf(t0.x, m0, a0.x); a0.y = fmaf(t0.y, m0, a0.y);
            a0.z = fmaf(t0.z, m0, a0.z); a0.w = fmaf(t0.w, m0, a0.w);
        }
        float4 v;
        v.x = a0.x + a1.x + bias4.x;
        v.y = a0.y + a1.y + bias4.y;
        v.z = a0.z + a1.z + bias4.z;
        v.w = a0.w + a1.w + bias4.w;
        if (BNRELU) {
            v.x = fmaxf(fmaf(v.x, bnw4.x, bnb4.x), 0.0f);
            v.y = fmaxf(fmaf(v.y, bnw4.y, bnb4.y), 0.0f);
            v.z = fmaxf(fmaf(v.z, bnw4.z, bnb4.z), 0.0f);
            v.w = fmaxf(fmaf(v.w, bnw4.w, bnb4.w), 0.0f);
            ((float4*)smH)[n * 33 + lane] = v;   // row-major, conflict-free
        } else {
            ((float4*)gout)[n * 32 + lane] = v;
        }
    }
}

// ---------------- fused whole-network kernel ---------------------------------
// smem: T[160*132] | H[160*132] (layer-0 A staging aliased) | W[2*16*128]
//       | edges | ptr
#define SMEM_FUSED ((2 * NNP * TS + 2 * 16 * CH) * 4 + ETOT * 8 + (NN + 1) * 4)

__global__ void __launch_bounds__(512, 1) fused_kernel(
    const float* __restrict__ x,
    const float* __restrict__ W0, const float* __restrict__ b0,
    const float* __restrict__ bnw0, const float* __restrict__ bnb0,
    const float* __restrict__ W1, const float* __restrict__ b1,
    const float* __restrict__ bnw1, const float* __restrict__ bnb1,
    const float* __restrict__ W2, const float* __restrict__ b2,
    float* __restrict__ out)
{
    extern __shared__ float sm[];
    float* smT = sm;                     // [160*132]
    float* smH = sm + NNP * TS;          // [160*132]  (smA aliases front)
    float* smW = smH + NNP * TS;         // [2*16*128]
    int2*  edg = (int2*)(smW + 2 * 16 * CH);
    int*   ptr = (int*)(edg + ETOT);

    const int tid = threadIdx.x;
    const int b   = blockIdx.x;

    // stage edge list (first use after multiple barriers)
    for (int i = tid; i < ETOT; i += 512) edg[i] = g_edge[i];
    if (tid <= NN) ptr[tid] = g_ptr[tid];

    // ---- layer 0 ----
    gemm_phase<true>(tid, CIN, 19, x + (size_t)b * NN * CIN, W0,
                     smT, nullptr, smH, smW);
    __syncthreads();
    agg_phase<true>(tid, smT, smH, nullptr, ptr, edg, b0, bnw0, bnb0);
    // zero H rows 156..159 once (agg never touches them again)
    if (tid < 128)
        ((float4*)smH)[(NN + (tid >> 5)) * 33 + (tid & 31)] =
            make_float4(0, 0, 0, 0);
    __syncthreads();

    // ---- layer 1 ----
    gemm_phase<false>(tid, CH, 8, nullptr, W1, smT, smH, nullptr, smW);
    __syncthreads();
    agg_phase<true>(tid, smT, smH, nullptr, ptr, edg, b1, bnw1, bnb1);
    __syncthreads();

    // ---- layer 2 ----
    gemm_phase<false>(tid, CH, 8, nullptr, W2, smT, smH, nullptr, smW);
    __syncthreads();
    agg_phase<false>(tid, smT, nullptr, out + (size_t)b * NN * CH,
                     ptr, edg, b2, nullptr, nullptr);
}

// ---------------- launch ----------------------------------------------------
extern "C" void kernel_launch(void* const* d_in, const int* in_sizes, int n_in,
                              void* d_out, int out_size)
{
    const float* x    = (const float*)d_in[0];
    const void*  ei   = d_in[1];
    const float* W0   = (const float*)d_in[2];
    const float* b0   = (const float*)d_in[3];
    const float* bnw0 = (const float*)d_in[4];
    const float* bnb0 = (const float*)d_in[5];
    const float* W1   = (const float*)d_in[6];
    const float* b1   = (const float*)d_in[7];
    const float* bnw1 = (const float*)d_in[8];
    const float* bnb1 = (const float*)d_in[9];
    const float* W2   = (const float*)d_in[10];
    const float* b2   = (const float*)d_in[11];
    float*       out  = (float*)d_out;

    cudaFuncSetAttribute(fused_kernel,
                         cudaFuncAttributeMaxDynamicSharedMemorySize, SMEM_FUSED);

    build_kernel<<<1, 256>>>(ei);
    fused_kernel<<<BATCH, 512, SMEM_FUSED>>>(
        x, W0, b0, bnw0, bnb0, W1, b1, bnw1, bnb1, W2, b2, out);
}

// round 9
// speedup vs baseline: 2.2833x; 2.2833x over previous
#include <cuda_runtime.h>
#include <cuda_bf16.h>
#include <cstdint>

// Problem constants
#define BATCH 1024
#define NN    156
#define CIN   301
#define CH    128
#define EDGES 1564
#define ETOT  (EDGES + NN)      // 1720
#define MTOT  (BATCH * NN)      // 159744
#define BN_INV_SQRT 0.9999950000374997f

// W-chunk slots: L0 = 5 chunks (Kpad 320), L1 = 2, L2 = 2  -> 9 slots
#define NSLOT 9
#define CHUNK_ELEMS (128 * 64)   // bf16 per slot (per hi/lo)
#define AW 36                    // smem row stride in 32-bit words (64 bf16 + pad)

// ---------------- scratch (static device memory) ----------------------------
__device__ float g_S0[(size_t)MTOT * CH];
__device__ float g_S1[(size_t)MTOT * CH];
__device__ int   g_ptr[NN + 1];
__device__ int2  g_edge[ETOT];
__device__ __nv_bfloat16 g_WtHi[NSLOT * CHUNK_ELEMS];   // [slot][n][k] bf16
__device__ __nv_bfloat16 g_WtLo[NSLOT * CHUNK_ELEMS];

// ---------------- helpers ----------------------------------------------------
__device__ __forceinline__ uint32_t bf16x2_pack(float lo_elem, float hi_elem) {
    // packs lo_elem into low half, hi_elem into high half
    uint32_t r;
    asm("cvt.rn.bf16x2.f32 %0, %1, %2;" : "=r"(r) : "f"(hi_elem), "f"(lo_elem));
    return r;
}
__device__ __forceinline__ void mma16816(float* c, const uint32_t* a,
                                         uint32_t b0, uint32_t b1) {
    asm volatile(
        "mma.sync.aligned.m16n8k16.row.col.f32.bf16.bf16.f32 "
        "{%0,%1,%2,%3}, {%4,%5,%6,%7}, {%8,%9}, {%0,%1,%2,%3};"
        : "+f"(c[0]), "+f"(c[1]), "+f"(c[2]), "+f"(c[3])
        : "r"(a[0]), "r"(a[1]), "r"(a[2]), "r"(a[3]), "r"(b0), "r"(b1));
}

// ---------------- kernel 1: graph preprocessing -> packed CSC ---------------
__global__ void build_kernel(const void* __restrict__ eiv) {
    const int* e32 = (const int*)eiv;
    __shared__ int   is64;
    __shared__ float deg[NN];
    __shared__ float dinv[NN];
    __shared__ int   cnt[NN];
    __shared__ int   base[NN + 1];
    int tid = threadIdx.x;

    if (tid == 0) {
        int all_zero = 1;
        for (int i = 1; i < 129; i += 2)
            if (e32[i] != 0) { all_zero = 0; break; }
        is64 = all_zero;
    }
    if (tid < NN) { deg[tid] = 1.0f; cnt[tid] = 1; }
    __syncthreads();

    const int stride64 = is64;
    auto fetch = [&](int i) -> int {
        int v = e32[i << stride64];
        return min(max(v, 0), NN - 1);
    };

    for (int e = tid; e < EDGES; e += blockDim.x) {
        int cl = fetch(EDGES + e);
        atomicAdd(&deg[cl], 1.0f);
        atomicAdd(&cnt[cl], 1);
    }
    __syncthreads();
    if (tid < NN) dinv[tid] = rsqrtf(deg[tid]);
    if (tid == 0) {
        int run = 0;
        for (int n = 0; n < NN; n++) { base[n] = run; run += cnt[n]; }
        base[NN] = run;
    }
    __syncthreads();
    if (tid <= NN) g_ptr[tid] = base[tid];
    if (tid < NN) cnt[tid] = base[tid];
    __syncthreads();

    for (int e = tid; e < EDGES; e += blockDim.x) {
        int r  = fetch(e);
        int cl = fetch(EDGES + e);
        int pos = atomicAdd(&cnt[cl], 1);
        g_edge[pos] = make_int2(r, __float_as_int(dinv[r] * dinv[cl]));
    }
    __syncthreads();
    for (int n = tid; n < NN; n += blockDim.x) {
        int pos = atomicAdd(&cnt[n], 1);
        g_edge[pos] = make_int2(n, __float_as_int(dinv[n] * dinv[n]));
    }
}

// ---------------- kernel 2: W prep: split + transpose ------------------------
// slots 0..4 -> W0 (K=301, pad 320); 5..6 -> W1; 7..8 -> W2.
// Output: [slot][n=128][k=64] bf16 hi/lo, linear (no swizzle).
__global__ void wprep_kernel(const float* __restrict__ W0,
                             const float* __restrict__ W1,
                             const float* __restrict__ W2) {
    int gid = blockIdx.x * blockDim.x + threadIdx.x;
    if (gid >= NSLOT * CHUNK_ELEMS) return;
    int slot = gid >> 13;
    int rem  = gid & 8191;
    int n = rem >> 6;
    int k = rem & 63;
    const float* W; int K; int c0;
    if (slot < 5)      { W = W0; K = CIN; c0 = slot; }
    else if (slot < 7) { W = W1; K = CH;  c0 = slot - 5; }
    else               { W = W2; K = CH;  c0 = slot - 7; }
    int kg = c0 * 64 + k;
    float v = (kg < K) ? W[(size_t)kg * CH + n] : 0.0f;
    __nv_bfloat16 hi = __float2bfloat16(v);
    __nv_bfloat16 lo = __float2bfloat16(v - __bfloat162float(hi));
    g_WtHi[gid] = hi;
    g_WtLo[gid] = lo;
}

// ---------------- kernel 3: HMMA bf16-split GEMM -----------------------------
// out[M,128] = A[M,K] @ W[K,128] fp32, via 3x bf16 mma.sync passes.
// 256 threads = 8 warps (4 along M x 2 along N); warp tile 32x64.
// smem: Ahi | Alo | Bhi | Blo, each [128][AW] u32 words (18432 B) = 73728 B.
#define GEMM_SMEM (4 * 128 * AW * 4)

__global__ void __launch_bounds__(256, 2) gemm_tc(
    const float* __restrict__ A, int K, int nchunks,
    const __nv_bfloat16* __restrict__ wtHi,
    const __nv_bfloat16* __restrict__ wtLo,
    float* __restrict__ out)
{
    extern __shared__ uint32_t sm[];
    uint32_t* sAh = sm;
    uint32_t* sAl = sm + 128 * AW;
    uint32_t* sBh = sm + 2 * 128 * AW;
    uint32_t* sBl = sm + 3 * 128 * AW;

    const int tid  = threadIdx.x;
    const int wid  = tid >> 5;
    const int lane = tid & 31;
    const int g    = lane >> 2;      // group 0..7
    const int tig  = lane & 3;       // thread-in-group
    const int warpM = wid & 3;       // 0..3  (32 rows each)
    const int warpN = wid >> 2;      // 0..1  (64 cols each)
    const size_t m0 = (size_t)blockIdx.x * 128;

    float acc[2][8][4];
#pragma unroll
    for (int mf = 0; mf < 2; mf++)
#pragma unroll
        for (int nf = 0; nf < 8; nf++)
#pragma unroll
            for (int q = 0; q < 4; q++) acc[mf][nf][q] = 0.0f;

    const uint32_t* gh32 = (const uint32_t*)wtHi;
    const uint32_t* gl32 = (const uint32_t*)wtLo;

    const int awb = (warpM * 32 + g) * AW + tig;
    const int bwb = (warpN * 64 + g) * AW + tig;

    for (int t = 0; t < nchunks; t++) {
        if (t) __syncthreads();   // previous compute done before restage

        // ---- stage A (split to hi/lo) ----
#pragma unroll
        for (int p = 0; p < 16; p++) {
            int idx = tid + p * 256;          // 0..4095
            int m = idx >> 5, kp = idx & 31;
            int kg = t * 64 + kp * 2;
            const float* ap = A + (m0 + m) * (size_t)K + kg;
            float v0 = (kg < K)     ? ap[0] : 0.0f;
            float v1 = (kg + 1 < K) ? ap[1] : 0.0f;
            float h0f = __bfloat162float(__float2bfloat16(v0));
            float h1f = __bfloat162float(__float2bfloat16(v1));
            sAh[m * AW + kp] = bf16x2_pack(h0f, h1f);
            sAl[m * AW + kp] = bf16x2_pack(v0 - h0f, v1 - h1f);
        }
        // ---- stage B (copy pre-split [n][k] images) ----
        const uint32_t* gh = gh32 + t * 4096;
        const uint32_t* gl = gl32 + t * 4096;
#pragma unroll
        for (int p = 0; p < 16; p++) {
            int idx = tid + p * 256;
            int n = idx >> 5, w = idx & 31;
            sBh[n * AW + w] = gh[n * 32 + w];
            sBl[n * AW + w] = gl[n * 32 + w];
        }
        __syncthreads();

        // ---- compute: 4 k16 steps ----
#pragma unroll
        for (int ks = 0; ks < 4; ks++) {
            uint32_t ah[2][4], al[2][4];
#pragma unroll
            for (int mf = 0; mf < 2; mf++) {
                int a0 = awb + mf * 16 * AW + ks * 8;
                ah[mf][0] = sAh[a0];
                ah[mf][1] = sAh[a0 + 8 * AW];
                ah[mf][2] = sAh[a0 + 4];
                ah[mf][3] = sAh[a0 + 8 * AW + 4];
                al[mf][0] = sAl[a0];
                al[mf][1] = sAl[a0 + 8 * AW];
                al[mf][2] = sAl[a0 + 4];
                al[mf][3] = sAl[a0 + 8 * AW + 4];
            }
#pragma unroll
            for (int nf = 0; nf < 8; nf++) {
                int b0 = bwb + nf * 8 * AW + ks * 8;
                uint32_t bh0 = sBh[b0], bh1 = sBh[b0 + 4];
                uint32_t bl0 = sBl[b0], bl1 = sBl[b0 + 4];
#pragma unroll
                for (int mf = 0; mf < 2; mf++) {
                    mma16816(acc[mf][nf], ah[mf], bh0, bh1);
                    mma16816(acc[mf][nf], ah[mf], bl0, bl1);
                    mma16816(acc[mf][nf], al[mf], bh0, bh1);
                }
            }
        }
    }

    // ---- epilogue: fragments -> global (float2, 8B aligned) ----
#pragma unroll
    for (int mf = 0; mf < 2; mf++) {
#pragma unroll
        for (int nf = 0; nf < 8; nf++) {
            int row = (int)(warpM * 32 + mf * 16 + g);
            int col = warpN * 64 + nf * 8 + tig * 2;
            float* o0 = out + (m0 + row) * CH + col;
            float* o1 = o0 + 8 * CH;
            *(float2*)o0 = make_float2(acc[mf][nf][0], acc[mf][nf][1]);
            *(float2*)o1 = make_float2(acc[mf][nf][2], acc[mf][nf][3]);
        }
    }
}

// ---------------- kernel 4: agg (R5-proven: smem staged, warp-per-row) ------
#define AGG_SMEM (NN * CH * 4 + ETOT * 8 + (NN + 1) * 4)

__global__ void __launch_bounds__(512, 2) agg_kernel(
    const float* __restrict__ T, float* __restrict__ out,
    const float* __restrict__ bias,
    const float* __restrict__ bnw, const float* __restrict__ bnb,
    int do_bnrelu)
{
    extern __shared__ float smf[];
    float4* Ts4   = (float4*)smf;                    // [NN*32]
    int2*   edg_s = (int2*)(smf + NN * CH);          // [ETOT]
    int*    ptr_s = (int*)(edg_s + ETOT);            // [NN+1]

    const int tid  = threadIdx.x;
    const int warp = tid >> 5;
    const int lane = tid & 31;
    const int b    = blockIdx.x;

    {
        const float4* Tb4 = (const float4*)(T + (size_t)b * NN * CH);
#pragma unroll
        for (int i = tid; i < NN * 32; i += 512) Ts4[i] = Tb4[i];
    }
    for (int i = tid; i < ETOT; i += 512) edg_s[i] = g_edge[i];
    if (tid <= NN) ptr_s[tid] = g_ptr[tid];
    __syncthreads();

    float4 bias4 = ((const float4*)bias)[lane];
    float4 bnw4 = make_float4(0, 0, 0, 0), bnb4 = make_float4(0, 0, 0, 0);
    if (do_bnrelu) {
        bnw4 = ((const float4*)bnw)[lane];
        bnw4.x *= BN_INV_SQRT; bnw4.y *= BN_INV_SQRT;
        bnw4.z *= BN_INV_SQRT; bnw4.w *= BN_INV_SQRT;
        bnb4 = ((const float4*)bnb)[lane];
    }

    float4* ob4 = (float4*)(out + (size_t)b * NN * CH);
    for (int n = warp; n < NN; n += 16) {
        int e = ptr_s[n];
        const int end = ptr_s[n + 1];
        float4 a0 = make_float4(0, 0, 0, 0);
        float4 a1 = make_float4(0, 0, 0, 0);
        for (; e + 1 < end; e += 2) {
            int2 e0 = edg_s[e], e1 = edg_s[e + 1];
            float4 t0 = Ts4[e0.x * 32 + lane];
            float4 t1 = Ts4[e1.x * 32 + lane];
            float m0 = __int_as_float(e0.y);
            float m1 = __int_as_float(e1.y);
            a0.x = fmaf(t0.x, m0, a0.x); a0.y = fmaf(t0.y, m0, a0.y);
            a0.z = fmaf(t0.z, m0, a0.z); a0.w = fmaf(t0.w, m0, a0.w);
            a1.x = fmaf(t1.x, m1, a1.x); a1.y = fmaf(t1.y, m1, a1.y);
            a1.z = fmaf(t1.z, m1, a1.z); a1.w = fmaf(t1.w, m1, a1.w);
        }
        if (e < end) {
            int2 e0 = edg_s[e];
            float4 t0 = Ts4[e0.x * 32 + lane];
            float m0 = __int_as_float(e0.y);
            a0.x = fmaf(t0.x, m0, a0.x); a0.y = fmaf(t0.y, m0, a0.y);
            a0.z = fmaf(t0.z, m0, a0.z); a0.w = fmaf(t0.w, m0, a0.w);
        }
        float4 v;
        v.x = a0.x + a1.x + bias4.x;
        v.y = a0.y + a1.y + bias4.y;
        v.z = a0.z + a1.z + bias4.z;
        v.w = a0.w + a1.w + bias4.w;
        if (do_bnrelu) {
            v.x = fmaxf(fmaf(v.x, bnw4.x, bnb4.x), 0.0f);
            v.y = fmaxf(fmaf(v.y, bnw4.y, bnb4.y), 0.0f);
            v.z = fmaxf(fmaf(v.z, bnw4.z, bnb4.z), 0.0f);
            v.w = fmaxf(fmaf(v.w, bnw4.w, bnb4.w), 0.0f);
        }
        ob4[n * 32 + lane] = v;
    }
}

// ---------------- launch ----------------------------------------------------
extern "C" void kernel_launch(void* const* d_in, const int* in_sizes, int n_in,
                              void* d_out, int out_size)
{
    const float* x    = (const float*)d_in[0];
    const void*  ei   = d_in[1];
    const float* W0   = (const float*)d_in[2];
    const float* b0   = (const float*)d_in[3];
    const float* bnw0 = (const float*)d_in[4];
    const float* bnb0 = (const float*)d_in[5];
    const float* W1   = (const float*)d_in[6];
    const float* b1   = (const float*)d_in[7];
    const float* bnw1 = (const float*)d_in[8];
    const float* bnb1 = (const float*)d_in[9];
    const float* W2   = (const float*)d_in[10];
    const float* b2   = (const float*)d_in[11];
    float*       out  = (float*)d_out;

    float *s0, *s1;
    __nv_bfloat16 *wh, *wl;
    cudaGetSymbolAddress((void**)&s0, g_S0);
    cudaGetSymbolAddress((void**)&s1, g_S1);
    cudaGetSymbolAddress((void**)&wh, g_WtHi);
    cudaGetSymbolAddress((void**)&wl, g_WtLo);

    cudaFuncSetAttribute(gemm_tc,
                         cudaFuncAttributeMaxDynamicSharedMemorySize, GEMM_SMEM);
    cudaFuncSetAttribute(agg_kernel,
                         cudaFuncAttributeMaxDynamicSharedMemorySize, AGG_SMEM);

    const int gridM = MTOT / 128;   // 1248

    build_kernel<<<1, 256>>>(ei);                                     // 1
    wprep_kernel<<<(NSLOT * CHUNK_ELEMS + 511) / 512, 512>>>(W0, W1, W2); // 2

    // layer 0  (K=301 -> 5 chunks; slots 0..4)
    gemm_tc<<<gridM, 256, GEMM_SMEM>>>(x, CIN, 5, wh, wl, s0);        // 3
    agg_kernel<<<BATCH, 512, AGG_SMEM>>>(s0, s1, b0, bnw0, bnb0, 1);  // 4
    // layer 1  (slots 5..6)
    gemm_tc<<<gridM, 256, GEMM_SMEM>>>(s1, CH, 2,
        wh + 5 * CHUNK_ELEMS, wl + 5 * CHUNK_ELEMS, s0);              // 5
    agg_kernel<<<BATCH, 512, AGG_SMEM>>>(s0, s1, b1, bnw1, bnb1, 1);  // 6 <- ncu
    // layer 2  (slots 7..8)
    gemm_tc<<<gridM, 256, GEMM_SMEM>>>(s1, CH, 2,
        wh + 7 * CHUNK_ELEMS, wl + 7 * CHUNK_ELEMS, s0);              // 7
    agg_kernel<<<BATCH, 512, AGG_SMEM>>>(s0, out, b2, nullptr, nullptr, 0); // 8
}

// round 10
// speedup vs baseline: 2.3644x; 1.0355x over previous
#include <cuda_runtime.h>
#include <cuda_bf16.h>
#include <cstdint>

// Problem constants
#define BATCH 1024
#define NN    156
#define CIN   301
#define CH    128
#define EDGES 1564
#define ETOT  (EDGES + NN)      // 1720
#define MTOT  (BATCH * NN)      // 159744
#define BN_INV_SQRT 0.9999950000374997f

// W-chunk slots: L0 = 5 chunks (Kpad 320), L1 = 2, L2 = 2  -> 9 slots
#define NSLOT 9
#define CHUNK_ELEMS (128 * 64)   // bf16 per slot (per hi/lo)
#define AW 36                    // smem row stride in 32-bit words
#define AWB (AW * 4)             // ... in bytes (144)

// ---------------- scratch (static device memory) ----------------------------
__device__ float g_S0[(size_t)MTOT * CH];
__device__ float g_S1[(size_t)MTOT * CH];
__device__ int   g_ptr[NN + 1];
__device__ int2  g_edge[ETOT];
__device__ __nv_bfloat16 g_WtHi[NSLOT * CHUNK_ELEMS];   // [slot][n][k] bf16
__device__ __nv_bfloat16 g_WtLo[NSLOT * CHUNK_ELEMS];

// ---------------- helpers ----------------------------------------------------
__device__ __forceinline__ uint32_t bf16x2_pack(float lo_elem, float hi_elem) {
    uint32_t r;
    asm("cvt.rn.bf16x2.f32 %0, %1, %2;" : "=r"(r) : "f"(hi_elem), "f"(lo_elem));
    return r;
}
__device__ __forceinline__ void mma16816(float* c, const uint32_t* a,
                                         uint32_t b0, uint32_t b1) {
    asm volatile(
        "mma.sync.aligned.m16n8k16.row.col.f32.bf16.bf16.f32 "
        "{%0,%1,%2,%3}, {%4,%5,%6,%7}, {%8,%9}, {%0,%1,%2,%3};"
        : "+f"(c[0]), "+f"(c[1]), "+f"(c[2]), "+f"(c[3])
        : "r"(a[0]), "r"(a[1]), "r"(a[2]), "r"(a[3]), "r"(b0), "r"(b1));
}
__device__ __forceinline__ void ldsm_x4(uint32_t* r, uint32_t addr) {
    asm volatile(
        "ldmatrix.sync.aligned.m8n8.x4.shared.b16 {%0,%1,%2,%3}, [%4];"
        : "=r"(r[0]), "=r"(r[1]), "=r"(r[2]), "=r"(r[3]) : "r"(addr));
}
__device__ __forceinline__ uint32_t smem_u32(const void* p) {
    uint32_t a;
    asm("{ .reg .u64 t; cvta.to.shared.u64 t, %1; cvt.u32.u64 %0, t; }"
        : "=r"(a) : "l"(p));
    return a;
}

// ---------------- kernel 1: graph preprocessing -> packed CSC ---------------
__global__ void build_kernel(const void* __restrict__ eiv) {
    const int* e32 = (const int*)eiv;
    __shared__ int   is64;
    __shared__ float deg[NN];
    __shared__ float dinv[NN];
    __shared__ int   cnt[NN];
    __shared__ int   base[NN + 1];
    int tid = threadIdx.x;

    if (tid == 0) {
        int all_zero = 1;
        for (int i = 1; i < 129; i += 2)
            if (e32[i] != 0) { all_zero = 0; break; }
        is64 = all_zero;
    }
    if (tid < NN) { deg[tid] = 1.0f; cnt[tid] = 1; }
    __syncthreads();

    const int stride64 = is64;
    auto fetch = [&](int i) -> int {
        int v = e32[i << stride64];
        return min(max(v, 0), NN - 1);
    };

    for (int e = tid; e < EDGES; e += blockDim.x) {
        int cl = fetch(EDGES + e);
        atomicAdd(&deg[cl], 1.0f);
        atomicAdd(&cnt[cl], 1);
    }
    __syncthreads();
    if (tid < NN) dinv[tid] = rsqrtf(deg[tid]);
    if (tid == 0) {
        int run = 0;
        for (int n = 0; n < NN; n++) { base[n] = run; run += cnt[n]; }
        base[NN] = run;
    }
    __syncthreads();
    if (tid <= NN) g_ptr[tid] = base[tid];
    if (tid < NN) cnt[tid] = base[tid];
    __syncthreads();

    for (int e = tid; e < EDGES; e += blockDim.x) {
        int r  = fetch(e);
        int cl = fetch(EDGES + e);
        int pos = atomicAdd(&cnt[cl], 1);
        g_edge[pos] = make_int2(r, __float_as_int(dinv[r] * dinv[cl]));
    }
    __syncthreads();
    for (int n = tid; n < NN; n += blockDim.x) {
        int pos = atomicAdd(&cnt[n], 1);
        g_edge[pos] = make_int2(n, __float_as_int(dinv[n] * dinv[n]));
    }
}

// ---------------- kernel 2: W prep: split + transpose ------------------------
__global__ void wprep_kernel(const float* __restrict__ W0,
                             const float* __restrict__ W1,
                             const float* __restrict__ W2) {
    int gid = blockIdx.x * blockDim.x + threadIdx.x;
    if (gid >= NSLOT * CHUNK_ELEMS) return;
    int slot = gid >> 13;
    int rem  = gid & 8191;
    int n = rem >> 6;
    int k = rem & 63;
    const float* W; int K; int c0;
    if (slot < 5)      { W = W0; K = CIN; c0 = slot; }
    else if (slot < 7) { W = W1; K = CH;  c0 = slot - 5; }
    else               { W = W2; K = CH;  c0 = slot - 7; }
    int kg = c0 * 64 + k;
    float v = (kg < K) ? W[(size_t)kg * CH + n] : 0.0f;
    __nv_bfloat16 hi = __float2bfloat16(v);
    __nv_bfloat16 lo = __float2bfloat16(v - __bfloat162float(hi));
    g_WtHi[gid] = hi;
    g_WtLo[gid] = lo;
}

// ---------------- kernel 3: HMMA bf16-split GEMM (ldmatrix) ------------------
// out[M,128] = A[M,K] @ W[K,128] fp32, 3x bf16 mma.sync passes.
// 256 threads = 8 warps (4 M x 2 N); warp tile 32x64.
// smem: Ahi | Alo | Bhi | Blo, each [128][AW] u32 words -> 73728 B.
#define GEMM_SMEM (4 * 128 * AW * 4)

__global__ void __launch_bounds__(256, 2) gemm_tc(
    const float* __restrict__ A, int K, int nchunks,
    const __nv_bfloat16* __restrict__ wtHi,
    const __nv_bfloat16* __restrict__ wtLo,
    float* __restrict__ out)
{
    extern __shared__ uint32_t sm[];
    uint32_t* sAh = sm;
    uint32_t* sAl = sm + 128 * AW;
    uint32_t* sBh = sm + 2 * 128 * AW;
    uint32_t* sBl = sm + 3 * 128 * AW;

    const int tid  = threadIdx.x;
    const int wid  = tid >> 5;
    const int lane = tid & 31;
    const int g    = lane >> 2;
    const int tig  = lane & 3;
    const int warpM = wid & 3;       // 0..3 (32 rows)
    const int warpN = wid >> 2;      // 0..1 (64 cols)
    const size_t m0 = (size_t)blockIdx.x * 128;

    float acc[2][8][4];
#pragma unroll
    for (int mf = 0; mf < 2; mf++)
#pragma unroll
        for (int nf = 0; nf < 8; nf++)
#pragma unroll
            for (int q = 0; q < 4; q++) acc[mf][nf][q] = 0.0f;

    const uint32_t* gh32 = (const uint32_t*)wtHi;
    const uint32_t* gl32 = (const uint32_t*)wtLo;

    // ldmatrix per-lane base addresses
    // A: matrices {m0-7 klo, m8-15 klo, m0-7 khi, m8-15 khi}
    const int aRow   = warpM * 32 + (lane & 7) + ((lane >> 3) & 1) * 8;
    const uint32_t aKoff = ((lane >> 4) & 1) * 16;   // bytes
    // B: matrices {n0-7 klo, n0-7 khi, n8-15 klo, n8-15 khi}
    const int bRow   = warpN * 64 + (lane & 7) + ((lane >> 4) & 1) * 8;
    const uint32_t bKoff = ((lane >> 3) & 1) * 16;

    const uint32_t sAh_u = smem_u32(sAh), sAl_u = smem_u32(sAl);
    const uint32_t sBh_u = smem_u32(sBh), sBl_u = smem_u32(sBl);
    uint32_t aHiB[2], aLoB[2], bHiB[4], bLoB[4];
#pragma unroll
    for (int mf = 0; mf < 2; mf++) {
        uint32_t off = (uint32_t)(aRow + mf * 16) * AWB + aKoff;
        aHiB[mf] = sAh_u + off;
        aLoB[mf] = sAl_u + off;
    }
#pragma unroll
    for (int nfp = 0; nfp < 4; nfp++) {
        uint32_t off = (uint32_t)(bRow + nfp * 16) * AWB + bKoff;
        bHiB[nfp] = sBh_u + off;
        bLoB[nfp] = sBl_u + off;
    }

    for (int t = 0; t < nchunks; t++) {
        if (t) __syncthreads();

        // ---- stage A (split fp32 -> bf16 hi/lo) ----
#pragma unroll
        for (int p = 0; p < 16; p++) {
            int idx = tid + p * 256;          // 0..4095
            int m = idx >> 5, kp = idx & 31;
            int kg = t * 64 + kp * 2;
            const float* ap = A + (m0 + m) * (size_t)K + kg;
            float v0 = (kg < K)     ? ap[0] : 0.0f;
            float v1 = (kg + 1 < K) ? ap[1] : 0.0f;
            float h0f = __bfloat162float(__float2bfloat16(v0));
            float h1f = __bfloat162float(__float2bfloat16(v1));
            sAh[m * AW + kp] = bf16x2_pack(h0f, h1f);
            sAl[m * AW + kp] = bf16x2_pack(v0 - h0f, v1 - h1f);
        }
        // ---- stage B (copy pre-split [n][k] images) ----
        const uint32_t* gh = gh32 + t * 4096;
        const uint32_t* gl = gl32 + t * 4096;
#pragma unroll
        for (int p = 0; p < 16; p++) {
            int idx = tid + p * 256;
            int n = idx >> 5, w = idx & 31;
            sBh[n * AW + w] = gh[n * 32 + w];
            sBl[n * AW + w] = gl[n * 32 + w];
        }
        __syncthreads();

        // ---- compute: 4 k16 steps, ldmatrix-fed ----
#pragma unroll
        for (int ks = 0; ks < 4; ks++) {
            const uint32_t kb = (uint32_t)ks * 32;
            uint32_t ah[2][4], al[2][4];
            ldsm_x4(ah[0], aHiB[0] + kb);
            ldsm_x4(ah[1], aHiB[1] + kb);
            ldsm_x4(al[0], aLoB[0] + kb);
            ldsm_x4(al[1], aLoB[1] + kb);
#pragma unroll
            for (int nfp = 0; nfp < 4; nfp++) {
                uint32_t bh[4], bl[4];
                ldsm_x4(bh, bHiB[nfp] + kb);
                ldsm_x4(bl, bLoB[nfp] + kb);
#pragma unroll
                for (int h = 0; h < 2; h++) {
                    int nf = nfp * 2 + h;
                    uint32_t bh0 = bh[h * 2], bh1 = bh[h * 2 + 1];
                    uint32_t bl0 = bl[h * 2], bl1 = bl[h * 2 + 1];
#pragma unroll
                    for (int mf = 0; mf < 2; mf++) {
                        mma16816(acc[mf][nf], ah[mf], bh0, bh1);
                        mma16816(acc[mf][nf], ah[mf], bl0, bl1);
                        mma16816(acc[mf][nf], al[mf], bh0, bh1);
                    }
                }
            }
        }
    }

    // ---- epilogue: fragments -> global (float2) ----
#pragma unroll
    for (int mf = 0; mf < 2; mf++) {
#pragma unroll
        for (int nf = 0; nf < 8; nf++) {
            int row = warpM * 32 + mf * 16 + g;
            int col = warpN * 64 + nf * 8 + tig * 2;
            float* o0 = out + (m0 + row) * CH + col;
            float* o1 = o0 + 8 * CH;
            *(float2*)o0 = make_float2(acc[mf][nf][0], acc[mf][nf][1]);
            *(float2*)o1 = make_float2(acc[mf][nf][2], acc[mf][nf][3]);
        }
    }
}

// ---------------- kernel 4: agg (smem staged, warp-per-row) ------------------
#define AGG_SMEM (NN * CH * 4 + ETOT * 8 + (NN + 1) * 4)

__global__ void __launch_bounds__(512, 2) agg_kernel(
    const float* __restrict__ T, float* __restrict__ out,
    const float* __restrict__ bias,
    const float* __restrict__ bnw, const float* __restrict__ bnb,
    int do_bnrelu)
{
    extern __shared__ float smf[];
    float4* Ts4   = (float4*)smf;                    // [NN*32]
    int2*   edg_s = (int2*)(smf + NN * CH);          // [ETOT]
    int*    ptr_s = (int*)(edg_s + ETOT);            // [NN+1]

    const int tid  = threadIdx.x;
    const int warp = tid >> 5;
    const int lane = tid & 31;
    const int b    = blockIdx.x;

    {
        const float4* Tb4 = (const float4*)(T + (size_t)b * NN * CH);
#pragma unroll
        for (int i = tid; i < NN * 32; i += 512) Ts4[i] = Tb4[i];
    }
    for (int i = tid; i < ETOT; i += 512) edg_s[i] = g_edge[i];
    if (tid <= NN) ptr_s[tid] = g_ptr[tid];
    __syncthreads();

    float4 bias4 = ((const float4*)bias)[lane];
    float4 bnw4 = make_float4(0, 0, 0, 0), bnb4 = make_float4(0, 0, 0, 0);
    if (do_bnrelu) {
        bnw4 = ((const float4*)bnw)[lane];
        bnw4.x *= BN_INV_SQRT; bnw4.y *= BN_INV_SQRT;
        bnw4.z *= BN_INV_SQRT; bnw4.w *= BN_INV_SQRT;
        bnb4 = ((const float4*)bnb)[lane];
    }

    float4* ob4 = (float4*)(out + (size_t)b * NN * CH);
    for (int n = warp; n < NN; n += 16) {
        int e = ptr_s[n];
        const int end = ptr_s[n + 1];
        float4 a0 = make_float4(0, 0, 0, 0);
        float4 a1 = make_float4(0, 0, 0, 0);
        for (; e + 1 < end; e += 2) {
            int2 e0 = edg_s[e], e1 = edg_s[e + 1];
            float4 t0 = Ts4[e0.x * 32 + lane];
            float4 t1 = Ts4[e1.x * 32 + lane];
            float m0 = __int_as_float(e0.y);
            float m1 = __int_as_float(e1.y);
            a0.x = fmaf(t0.x, m0, a0.x); a0.y = fmaf(t0.y, m0, a0.y);
            a0.z = fmaf(t0.z, m0, a0.z); a0.w = fmaf(t0.w, m0, a0.w);
            a1.x = fmaf(t1.x, m1, a1.x); a1.y = fmaf(t1.y, m1, a1.y);
            a1.z = fmaf(t1.z, m1, a1.z); a1.w = fmaf(t1.w, m1, a1.w);
        }
        if (e < end) {
            int2 e0 = edg_s[e];
            float4 t0 = Ts4[e0.x * 32 + lane];
            float m0 = __int_as_float(e0.y);
            a0.x = fmaf(t0.x, m0, a0.x); a0.y = fmaf(t0.y, m0, a0.y);
            a0.z = fmaf(t0.z, m0, a0.z); a0.w = fmaf(t0.w, m0, a0.w);
        }
        float4 v;
        v.x = a0.x + a1.x + bias4.x;
        v.y = a0.y + a1.y + bias4.y;
        v.z = a0.z + a1.z + bias4.z;
        v.w = a0.w + a1.w + bias4.w;
        if (do_bnrelu) {
            v.x = fmaxf(fmaf(v.x, bnw4.x, bnb4.x), 0.0f);
            v.y = fmaxf(fmaf(v.y, bnw4.y, bnb4.y), 0.0f);
            v.z = fmaxf(fmaf(v.z, bnw4.z, bnb4.z), 0.0f);
            v.w = fmaxf(fmaf(v.w, bnw4.w, bnb4.w), 0.0f);
        }
        ob4[n * 32 + lane] = v;
    }
}

// ---------------- launch ----------------------------------------------------
extern "C" void kernel_launch(void* const* d_in, const int* in_sizes, int n_in,
                              void* d_out, int out_size)
{
    const float* x    = (const float*)d_in[0];
    const void*  ei   = d_in[1];
    const float* W0   = (const float*)d_in[2];
    const float* b0   = (const float*)d_in[3];
    const float* bnw0 = (const float*)d_in[4];
    const float* bnb0 = (const float*)d_in[5];
    const float* W1   = (const float*)d_in[6];
    const float* b1   = (const float*)d_in[7];
    const float* bnw1 = (const float*)d_in[8];
    const float* bnb1 = (const float*)d_in[9];
    const float* W2   = (const float*)d_in[10];
    const float* b2   = (const float*)d_in[11];
    float*       out  = (float*)d_out;

    float *s0, *s1;
    __nv_bfloat16 *wh, *wl;
    cudaGetSymbolAddress((void**)&s0, g_S0);
    cudaGetSymbolAddress((void**)&s1, g_S1);
    cudaGetSymbolAddress((void**)&wh, g_WtHi);
    cudaGetSymbolAddress((void**)&wl, g_WtLo);

    cudaFuncSetAttribute(gemm_tc,
                         cudaFuncAttributeMaxDynamicSharedMemorySize, GEMM_SMEM);
    cudaFuncSetAttribute(agg_kernel,
                         cudaFuncAttributeMaxDynamicSharedMemorySize, AGG_SMEM);

    const int gridM = MTOT / 128;   // 1248

    // build launched twice (idempotent) so ncu's skip-5 window (-s 5 -c 1)
    // lands on the K=128 gemm this round.
    build_kernel<<<1, 256>>>(ei);                                     // 1
    build_kernel<<<1, 256>>>(ei);                                     // 2
    wprep_kernel<<<(NSLOT * CHUNK_ELEMS + 511) / 512, 512>>>(W0, W1, W2); // 3

    // layer 0  (K=301 -> 5 chunks; slots 0..4)
    gemm_tc<<<gridM, 256, GEMM_SMEM>>>(x, CIN, 5, wh, wl, s0);        // 4
    agg_kernel<<<BATCH, 512, AGG_SMEM>>>(s0, s1, b0, bnw0, bnb0, 1);  // 5
    // layer 1  (slots 5..6)
    gemm_tc<<<gridM, 256, GEMM_SMEM>>>(s1, CH, 2,
        wh + 5 * CHUNK_ELEMS, wl + 5 * CHUNK_ELEMS, s0);              // 6 <- ncu
    agg_kernel<<<BATCH, 512, AGG_SMEM>>>(s0, s1, b1, bnw1, bnb1, 1);  // 7
    // layer 2  (slots 7..8)
    gemm_tc<<<gridM, 256, GEMM_SMEM>>>(s1, CH, 2,
        wh + 7 * CHUNK_ELEMS, wl + 7 * CHUNK_ELEMS, s0);              // 8
    agg_kernel<<<BATCH, 512, AGG_SMEM>>>(s0, out, b2, nullptr, nullptr, 0); // 9
}